// round 1
// baseline (speedup 1.0000x reference)
#include <cuda_runtime.h>
#include <math.h>

// Problem constants (fixed shapes for this problem)
#define BATCHV   4096
#define DIMV     100     // state dim
#define TSTEPS   100     // T-1 integration steps
#define WIDTHV   200     // MLP width

// Kernel config
#define NTHREADS 256
#define M_TILE   32      // batch rows per CTA  -> 128 CTAs
#define KC       40      // k-chunk rows staged in smem per cp.async stage
#define W_PAD    224     // padded weight/activation row width (32*7)
#define A_W      224     // activation buffer width
#define A0_W     104     // layer-0 input buffer width (1 + 100, padded to 104)

#define DW_STRIDE (DIMV * (TSTEPS + 1))   // 10100 floats per batch row of dW

// ---------------- cp.async helpers ----------------
__device__ __forceinline__ void cp_async16(void* sdst, const void* gsrc) {
    unsigned s = (unsigned)__cvta_generic_to_shared(sdst);
    asm volatile("cp.async.cg.shared.global [%0], [%1], 16;" :: "r"(s), "l"(gsrc));
}
__device__ __forceinline__ void cp_commit() {
    asm volatile("cp.async.commit_group;");
}
template<int N>
__device__ __forceinline__ void cp_wait() {
    asm volatile("cp.async.wait_group %0;" :: "n"(N));
}

// ---------------- per-layer GEMM ----------------
// Computes aOut[m, n] = act( aIn[m, :K] @ W[K, NV] + b[n] ) for one CTA tile
// (M_TILE rows). Thread (m_id, n_id) owns rows m_id*4..+3 and cols n_id+32*j.
// Weights are streamed global->smem in KC-row chunks, double buffered.
template<int NJ, int NV, bool RELU>
__device__ __forceinline__ void gemm_layer(
    const float* __restrict__ aIn, int lda,
    float* __restrict__ aOut,
    const float* __restrict__ gW, const float* __restrict__ gB,
    int K, float* __restrict__ ws,
    int m_id, int n_id, int tid)
{
    float acc[4][NJ];
    #pragma unroll
    for (int j = 0; j < NJ; ++j) {
        int n = n_id + 32 * j;
        float bv = (n < NV) ? gB[n] : 0.0f;
        #pragma unroll
        for (int i = 0; i < 4; ++i) acc[i][j] = bv;
    }

    const int nchunks = (K + KC - 1) / KC;

    // prefetch chunk 0 into buffer 0
    {
        int kc0 = (KC < K) ? KC : K;
        int nf4 = kc0 * NV / 4;           // NV divisible by 4 (200 or 100)
        for (int f = tid; f < nf4; f += NTHREADS) {
            int fi = f * 4;
            int r = fi / NV;
            int c = fi - r * NV;
            cp_async16(ws + r * W_PAD + c, gW + fi);
        }
        cp_commit();
    }

    for (int ch = 0; ch < nchunks; ++ch) {
        int k0 = ch * KC;
        int kc = K - k0; if (kc > KC) kc = KC;
        float* wbuf = ws + (ch & 1) * (KC * W_PAD);

        if (ch + 1 < nchunks) {
            // prefetch next chunk into the other buffer
            int k1 = k0 + KC;
            int kc1 = K - k1; if (kc1 > KC) kc1 = KC;
            float* wnext = ws + ((ch + 1) & 1) * (KC * W_PAD);
            const float* gsrc = gW + (size_t)k1 * NV;
            int nf4 = kc1 * NV / 4;
            for (int f = tid; f < nf4; f += NTHREADS) {
                int fi = f * 4;
                int r = fi / NV;
                int c = fi - r * NV;
                cp_async16(wnext + r * W_PAD + c, gsrc + fi);
            }
            cp_commit();
            cp_wait<1>();   // chunk ch landed
        } else {
            cp_wait<0>();
        }
        __syncthreads();    // all threads see chunk ch; prev buffer free

        const float* a0p = aIn + (m_id * 4 + 0) * lda + k0;
        const float* a1p = aIn + (m_id * 4 + 1) * lda + k0;
        const float* a2p = aIn + (m_id * 4 + 2) * lda + k0;
        const float* a3p = aIn + (m_id * 4 + 3) * lda + k0;
        const float* wp  = wbuf + n_id;

        #pragma unroll 4
        for (int k = 0; k < kc; ++k) {
            float a0 = a0p[k];
            float a1 = a1p[k];
            float a2 = a2p[k];
            float a3 = a3p[k];
            #pragma unroll
            for (int j = 0; j < NJ; ++j) {
                float w = wp[k * W_PAD + 32 * j];
                acc[0][j] = fmaf(a0, w, acc[0][j]);
                acc[1][j] = fmaf(a1, w, acc[1][j]);
                acc[2][j] = fmaf(a2, w, acc[2][j]);
                acc[3][j] = fmaf(a3, w, acc[3][j]);
            }
        }
        __syncthreads();    // done reading wbuf before it is refilled
    }

    #pragma unroll
    for (int j = 0; j < NJ; ++j) {
        #pragma unroll
        for (int i = 0; i < 4; ++i) {
            float v = acc[i][j];
            if (RELU) v = fmaxf(v, 0.0f);
            aOut[(m_id * 4 + i) * A_W + n_id + 32 * j] = v;
        }
    }
}

// ---------------- persistent trajectory kernel ----------------
// smem floats:
//   act0: M_TILE*A0_W  (3328)  [t | S] layer-0 input, S persists across steps
//   act1: M_TILE*A_W   (7168)
//   act2: M_TILE*A_W   (7168)
//   errs: M_TILE*DIMV  (3200)
//   ws:   2*KC*W_PAD   (17920) weight double buffer
// total = 38784 floats = 155136 bytes
#define SMEM_FLOATS (M_TILE*A0_W + 2*M_TILE*A_W + M_TILE*DIMV + 2*KC*W_PAD)
#define SMEM_BYTES  (SMEM_FLOATS * 4)

__global__ void __launch_bounds__(NTHREADS, 1)
control_solver_kernel(
    const float* __restrict__ S0,  const float* __restrict__ tg,
    const float* __restrict__ dW,
    const float* __restrict__ W0,  const float* __restrict__ b0,
    const float* __restrict__ W1,  const float* __restrict__ b1,
    const float* __restrict__ W2,  const float* __restrict__ b2,
    const float* __restrict__ W3,  const float* __restrict__ b3,
    const float* __restrict__ Wout, const float* __restrict__ bout,
    float* __restrict__ out)
{
    extern __shared__ float sm[];
    float* act0 = sm;                         // [M_TILE][A0_W]
    float* act1 = act0 + M_TILE * A0_W;       // [M_TILE][A_W]
    float* act2 = act1 + M_TILE * A_W;        // [M_TILE][A_W]
    float* errs = act2 + M_TILE * A_W;        // [M_TILE][DIMV]
    float* ws   = errs + M_TILE * DIMV;       // [2][KC][W_PAD]

    const int tid  = threadIdx.x;
    const int m_id = tid >> 5;                // 0..7   (4 rows each)
    const int n_id = tid & 31;                // 0..31
    const int gm0  = blockIdx.x * M_TILE;

    // init: zero weight staging (padding cols stay 0 forever), zero err, load S0
    for (int idx = tid; idx < 2 * KC * W_PAD; idx += NTHREADS) ws[idx] = 0.0f;
    for (int idx = tid; idx < M_TILE * DIMV; idx += NTHREADS) {
        errs[idx] = 0.0f;
        int m = idx / DIMV, n = idx - (idx / DIMV) * DIMV;
        act0[m * A0_W + 1 + n] = S0[(size_t)(gm0 + m) * DIMV + n];
    }
    const float h   = tg[1] - tg[0];
    const float sqh = sqrtf(h);
    __syncthreads();

    for (int t = 0; t < TSTEPS; ++t) {
        if (tid < M_TILE) act0[tid * A0_W] = tg[t];   // time feature column
        __syncthreads();

        gemm_layer<7, WIDTHV, true >(act0, A0_W, act1, W0,   b0,   DIMV + 1, ws, m_id, n_id, tid);
        gemm_layer<7, WIDTHV, true >(act1, A_W,  act2, W1,   b1,   WIDTHV,   ws, m_id, n_id, tid);
        gemm_layer<7, WIDTHV, true >(act2, A_W,  act1, W2,   b2,   WIDTHV,   ws, m_id, n_id, tid);
        gemm_layer<7, WIDTHV, true >(act1, A_W,  act2, W3,   b3,   WIDTHV,   ws, m_id, n_id, tid);
        gemm_layer<4, DIMV,   false>(act2, A_W,  act1, Wout, bout, WIDTHV,   ws, m_id, n_id, tid);
        __syncthreads();   // u available in act1

        // SDE update: err += u*u*h ; S += u*h + u*(sqrt(h)*dW[t])
        for (int idx = tid; idx < M_TILE * DIMV; idx += NTHREADS) {
            int m = idx / DIMV, n = idx - (idx / DIMV) * DIMV;
            float u = act1[m * A_W + n];
            errs[idx] = fmaf(u * u, h, errs[idx]);
            float dwi = sqh * dW[(size_t)(gm0 + m) * DW_STRIDE + t * DIMV + n];
            float S = act0[m * A0_W + 1 + n];
            act0[m * A0_W + 1 + n] = fmaf(u, h + dwi, S);
        }
        __syncthreads();
    }

    // out = err + S_final^2
    for (int idx = tid; idx < M_TILE * DIMV; idx += NTHREADS) {
        int m = idx / DIMV, n = idx - (idx / DIMV) * DIMV;
        float S = act0[m * A0_W + 1 + n];
        out[(size_t)(gm0 + m) * DIMV + n] = fmaf(S, S, errs[idx]);
    }
}

extern "C" void kernel_launch(void* const* d_in, const int* in_sizes, int n_in,
                              void* d_out, int out_size) {
    const float* S0   = (const float*)d_in[0];
    const float* tg   = (const float*)d_in[1];
    const float* dW   = (const float*)d_in[2];
    const float* W0   = (const float*)d_in[3];
    const float* b0   = (const float*)d_in[4];
    const float* W1   = (const float*)d_in[5];
    const float* b1   = (const float*)d_in[6];
    const float* W2   = (const float*)d_in[7];
    const float* b2   = (const float*)d_in[8];
    const float* W3   = (const float*)d_in[9];
    const float* b3   = (const float*)d_in[10];
    const float* Wout = (const float*)d_in[11];
    const float* bout = (const float*)d_in[12];
    float* out = (float*)d_out;

    cudaFuncSetAttribute(control_solver_kernel,
                         cudaFuncAttributeMaxDynamicSharedMemorySize, SMEM_BYTES);

    control_solver_kernel<<<BATCHV / M_TILE, NTHREADS, SMEM_BYTES>>>(
        S0, tg, dW, W0, b0, W1, b1, W2, b2, W3, b3, Wout, bout, out);
}

// round 2
// speedup vs baseline: 1.1976x; 1.1976x over previous
#include <cuda_runtime.h>
#include <math.h>

// Problem constants
#define BATCHV   4096
#define DIMV     100
#define TSTEPS   100     // T-1 integration steps
#define WIDTHV   200

// Kernel config
#define NTHREADS 256
#define M_TILE   32      // batch rows per CTA -> 128 CTAs
#define KC2      20      // k2 (k-pair) rows staged per cp.async stage
#define A_W      224     // activation buffer width (floats)
#define A0_W     104     // layer-0 input width (1+100 padded to 104, even)
#define WS_BUF   8000    // floats per weight stage buffer (KC2 * 400)

#define DW_STRIDE (DIMV * (TSTEPS + 1))   // 10100

typedef unsigned long long u64t;

// ---------------- packed f32x2 helpers ----------------
__device__ __forceinline__ u64t pack2(float lo, float hi) {
    u64t v; asm("mov.b64 %0, {%1, %2};" : "=l"(v) : "f"(lo), "f"(hi)); return v;
}
__device__ __forceinline__ float2 unpack2(u64t v) {
    float2 r; asm("mov.b64 {%0, %1}, %2;" : "=f"(r.x), "=f"(r.y) : "l"(v)); return r;
}
__device__ __forceinline__ u64t lds64(const float* p) {
    u64t v; unsigned a = (unsigned)__cvta_generic_to_shared(p);
    asm volatile("ld.shared.b64 %0, [%1];" : "=l"(v) : "r"(a));
    return v;
}
// d = a * b + d  (elementwise on packed f32 pairs) -> single FFMA2 SASS op
__device__ __forceinline__ void ffma2(u64t& d, u64t a, u64t b) {
    asm("fma.rn.f32x2 %0, %1, %2, %0;" : "+l"(d) : "l"(a), "l"(b));
}

// ---------------- cp.async helpers ----------------
__device__ __forceinline__ void cp_async16(void* sdst, const void* gsrc) {
    unsigned s = (unsigned)__cvta_generic_to_shared(sdst);
    asm volatile("cp.async.cg.shared.global [%0], [%1], 16;" :: "r"(s), "l"(gsrc));
}
__device__ __forceinline__ void cp_commit() { asm volatile("cp.async.commit_group;"); }
template<int N>
__device__ __forceinline__ void cp_wait() { asm volatile("cp.async.wait_group %0;" :: "n"(N)); }

// ---------------- pre-paired weight pool ----------------
// Layout per layer: [K2][N] of float2 = (W[2*k2][n], W[2*k2+1][n]), zero-padded odd K.
#define OFF_W0 0        // K2=51, N=200 -> 10200
#define OFF_W1 10200    // K2=100, N=200 -> 20000
#define OFF_W2 30200
#define OFF_W3 50200
#define OFF_WO 70200    // K2=100, N=100 -> 10000
__device__ float2 g_Wp[80200];

__global__ void pack_weights_kernel(const float* __restrict__ W, int K, int N, int off) {
    int idx = blockIdx.x * blockDim.x + threadIdx.x;
    int K2 = (K + 1) >> 1;
    if (idx >= K2 * N) return;
    int k2 = idx / N, n = idx - k2 * N;
    float lo = W[(2 * k2) * N + n];
    float hi = (2 * k2 + 1 < K) ? W[(2 * k2 + 1) * N + n] : 0.0f;
    g_Wp[off + idx] = make_float2(lo, hi);
}

// ---------------- per-layer GEMM (packed over k-parity) ----------------
// aOut[m, n] = act( aIn[m, 0:2*K2] @ W + b[n] )
// Thread (m_id, n_id) owns rows m_id*4..+3 and cols n_id + 32*j.
// acc[i][j] holds packed (even-k partial, odd-k partial); summed at the end.
template<int NJ, int NV, bool RELU>
__device__ __forceinline__ void gemm2(
    const float* __restrict__ aIn, int lda,
    float* __restrict__ aOut,
    const float2* __restrict__ gWp, const float* __restrict__ gB,
    int K2, float* __restrict__ ws,
    int m_id, int n_id, int tid)
{
    const int ROWF = 2 * NV;   // floats per k2 row in staged smem
    u64t acc[4][NJ];
    #pragma unroll
    for (int j = 0; j < NJ; ++j) {
        int n = n_id + 32 * j;
        float bv = (n < NV) ? gB[n] : 0.0f;
        u64t b2 = pack2(bv, 0.0f);
        #pragma unroll
        for (int i = 0; i < 4; ++i) acc[i][j] = b2;
    }

    const int nchunks = (K2 + KC2 - 1) / KC2;

    // prefetch chunk 0 into buffer 0
    {
        int kc0 = (KC2 < K2) ? KC2 : K2;
        int nf = kc0 * ROWF / 4;
        const float* gsrc = (const float*)gWp;
        for (int f = tid; f < nf; f += NTHREADS)
            cp_async16(ws + f * 4, gsrc + f * 4);
        cp_commit();
    }

    for (int ch = 0; ch < nchunks; ++ch) {
        int k20 = ch * KC2;
        int kc = K2 - k20; if (kc > KC2) kc = KC2;
        float* wbuf = ws + (ch & 1) * WS_BUF;

        if (ch + 1 < nchunks) {
            int k21 = k20 + KC2;
            int kc1 = K2 - k21; if (kc1 > KC2) kc1 = KC2;
            float* wn = ws + ((ch + 1) & 1) * WS_BUF;
            const float* gsrc = (const float*)(gWp + (size_t)k21 * NV);
            int nf = kc1 * ROWF / 4;
            for (int f = tid; f < nf; f += NTHREADS)
                cp_async16(wn + f * 4, gsrc + f * 4);
            cp_commit();
            cp_wait<1>();
        } else {
            cp_wait<0>();
        }
        __syncthreads();   // chunk visible; prev buffer free; prev layer stores visible

        const float* a0p = aIn + (m_id * 4 + 0) * lda + 2 * k20;
        const float* a1p = aIn + (m_id * 4 + 1) * lda + 2 * k20;
        const float* a2p = aIn + (m_id * 4 + 2) * lda + 2 * k20;
        const float* a3p = aIn + (m_id * 4 + 3) * lda + 2 * k20;
        const float* wp  = wbuf + 2 * n_id;

        #pragma unroll 4
        for (int k2 = 0; k2 < kc; ++k2) {
            u64t a0 = lds64(a0p + 2 * k2);
            u64t a1 = lds64(a1p + 2 * k2);
            u64t a2 = lds64(a2p + 2 * k2);
            u64t a3 = lds64(a3p + 2 * k2);
            #pragma unroll
            for (int j = 0; j < NJ; ++j) {
                u64t w = lds64(wp + k2 * ROWF + 64 * j);
                ffma2(acc[0][j], a0, w);
                ffma2(acc[1][j], a1, w);
                ffma2(acc[2][j], a2, w);
                ffma2(acc[3][j], a3, w);
            }
        }
        __syncthreads();   // done reading wbuf before refill
    }

    #pragma unroll
    for (int j = 0; j < NJ; ++j) {
        int n = n_id + 32 * j;
        #pragma unroll
        for (int i = 0; i < 4; ++i) {
            float2 v2 = unpack2(acc[i][j]);
            float v = v2.x + v2.y;
            if (RELU) v = fmaxf(v, 0.0f);
            if (n < NV) aOut[(m_id * 4 + i) * A_W + n] = v;
        }
    }
}

// ---------------- persistent trajectory kernel ----------------
// smem floats:
//   act0: 32*104 = 3328   [t | S | 0pad], S persists across steps
//   act1: 32*224 = 7168
//   act2: 32*224 = 7168
//   errs: 32*100 = 3200
//   ws:   2*8000 + 64 = 16064   (weight double buffer + tail-overread slack)
#define SMEM_FLOATS (M_TILE*A0_W + 2*M_TILE*A_W + M_TILE*DIMV + 2*WS_BUF + 64)
#define SMEM_BYTES  (SMEM_FLOATS * 4)

__global__ void __launch_bounds__(NTHREADS, 1)
control_solver_kernel(
    const float* __restrict__ S0,  const float* __restrict__ tg,
    const float* __restrict__ dW,
    const float* __restrict__ b0,  const float* __restrict__ b1,
    const float* __restrict__ b2,  const float* __restrict__ b3,
    const float* __restrict__ bout,
    float* __restrict__ out)
{
    extern __shared__ float sm[];
    float* act0 = sm;
    float* act1 = act0 + M_TILE * A0_W;
    float* act2 = act1 + M_TILE * A_W;
    float* errs = act2 + M_TILE * A_W;
    float* ws   = errs + M_TILE * DIMV;

    const int tid  = threadIdx.x;
    const int m_id = tid >> 5;
    const int n_id = tid & 31;
    const int gm0  = blockIdx.x * M_TILE;

    for (int idx = tid; idx < M_TILE * DIMV; idx += NTHREADS) {
        errs[idx] = 0.0f;
        int m = idx / DIMV, n = idx - (idx / DIMV) * DIMV;
        act0[m * A0_W + 1 + n] = S0[(size_t)(gm0 + m) * DIMV + n];
    }
    if (tid < M_TILE) {
        act0[tid * A0_W + 101] = 0.0f;   // zero-pad col for odd K of layer 0
        act0[tid * A0_W + 102] = 0.0f;
        act0[tid * A0_W + 103] = 0.0f;
    }
    const float h   = tg[1] - tg[0];
    const float sqh = sqrtf(h);
    __syncthreads();

    const float2* W0p = g_Wp + OFF_W0;
    const float2* W1p = g_Wp + OFF_W1;
    const float2* W2p = g_Wp + OFF_W2;
    const float2* W3p = g_Wp + OFF_W3;
    const float2* WOp = g_Wp + OFF_WO;

    for (int t = 0; t < TSTEPS; ++t) {
        if (tid < M_TILE) act0[tid * A0_W] = tg[t];
        __syncthreads();

        gemm2<7, WIDTHV, true >(act0, A0_W, act1, W0p, b0,   51,  ws, m_id, n_id, tid);
        gemm2<7, WIDTHV, true >(act1, A_W,  act2, W1p, b1,   100, ws, m_id, n_id, tid);
        gemm2<7, WIDTHV, true >(act2, A_W,  act1, W2p, b2,   100, ws, m_id, n_id, tid);
        gemm2<7, WIDTHV, true >(act1, A_W,  act2, W3p, b3,   100, ws, m_id, n_id, tid);
        gemm2<4, DIMV,   false>(act2, A_W,  act1, WOp, bout, 100, ws, m_id, n_id, tid);
        __syncthreads();   // u available in act1

        for (int idx = tid; idx < M_TILE * DIMV; idx += NTHREADS) {
            int m = idx / DIMV, n = idx - (idx / DIMV) * DIMV;
            float u = act1[m * A_W + n];
            errs[idx] = fmaf(u * u, h, errs[idx]);
            float dwi = sqh * dW[(size_t)(gm0 + m) * DW_STRIDE + t * DIMV + n];
            float S = act0[m * A0_W + 1 + n];
            act0[m * A0_W + 1 + n] = fmaf(u, h + dwi, S);
        }
        __syncthreads();
    }

    for (int idx = tid; idx < M_TILE * DIMV; idx += NTHREADS) {
        int m = idx / DIMV, n = idx - (idx / DIMV) * DIMV;
        float S = act0[m * A0_W + 1 + n];
        out[(size_t)(gm0 + m) * DIMV + n] = fmaf(S, S, errs[idx]);
    }
}

extern "C" void kernel_launch(void* const* d_in, const int* in_sizes, int n_in,
                              void* d_out, int out_size) {
    const float* S0   = (const float*)d_in[0];
    const float* tg   = (const float*)d_in[1];
    const float* dW   = (const float*)d_in[2];
    const float* W0   = (const float*)d_in[3];
    const float* b0   = (const float*)d_in[4];
    const float* W1   = (const float*)d_in[5];
    const float* b1   = (const float*)d_in[6];
    const float* W2   = (const float*)d_in[7];
    const float* b2   = (const float*)d_in[8];
    const float* W3   = (const float*)d_in[9];
    const float* b3   = (const float*)d_in[10];
    const float* Wout = (const float*)d_in[11];
    const float* bout = (const float*)d_in[12];
    float* out = (float*)d_out;

    // Pre-pair weights into (even-k, odd-k) float2 layout, zero-padded.
    pack_weights_kernel<<<(51  * 200 + 255) / 256, 256>>>(W0,   101, 200, OFF_W0);
    pack_weights_kernel<<<(100 * 200 + 255) / 256, 256>>>(W1,   200, 200, OFF_W1);
    pack_weights_kernel<<<(100 * 200 + 255) / 256, 256>>>(W2,   200, 200, OFF_W2);
    pack_weights_kernel<<<(100 * 200 + 255) / 256, 256>>>(W3,   200, 200, OFF_W3);
    pack_weights_kernel<<<(100 * 100 + 255) / 256, 256>>>(Wout, 200, 100, OFF_WO);

    cudaFuncSetAttribute(control_solver_kernel,
                         cudaFuncAttributeMaxDynamicSharedMemorySize, SMEM_BYTES);

    control_solver_kernel<<<BATCHV / M_TILE, NTHREADS, SMEM_BYTES>>>(
        S0, tg, dW, b0, b1, b2, b3, bout, out);
}